// round 14
// baseline (speedup 1.0000x reference)
#include <cuda_runtime.h>
#include <cstdint>

#define DIVUP(a,b) (((a)+(b)-1)/(b))

// ---------------- static scratch (no allocations allowed) ----------------
// Activations in NHWC layout: [n][h][w][c]
__device__ float g_a1[128*118*158*24];
__device__ float g_a2[128*57*77*36];
__device__ float g_a3[128*27*37*48];
__device__ float g_a4[128*25*35*64];
__device__ float g_a5[128*23*33*64];

__device__ float g_qw1[24*1*5*5];
__device__ float g_qw2[36*24*5*5];
__device__ float g_qw3[48*36*5*5];
__device__ float g_qw4[64*48*3*3];
__device__ float g_qw5[64*64*3*3];
__device__ float g_qfw1t[48576*100];     // fc1 weight: quantized, NHWC-permuted, [k][n]
__device__ float g_qfw2[50*100];
__device__ float g_qfw3[10*50];
__device__ float g_qow[10];

__device__ unsigned g_absmax[9];

#define FC1_SPLIT 32
__device__ float g_fc1part[FC1_SPLIT*128*100];
__device__ float g_f1[128*100];
__device__ float g_f2[128*50];
__device__ float g_f3[128*10];

// ---------------- merged weight fake-quant (exact fp32 semantics) ----------------
__global__ void k_reset_absmax() {
    if (threadIdx.x < 9) g_absmax[threadIdx.x] = 0u;
}

struct AbsArgs { const float* p[9]; int n[9]; };

__global__ void k_absmax_all(AbsArgs a) {
    const int slot = blockIdx.y;
    const float* __restrict__ w = a.p[slot];
    const int n = a.n[slot];
    float m = 0.f;
    for (int i = blockIdx.x * blockDim.x + threadIdx.x; i < n; i += gridDim.x * blockDim.x)
        m = fmaxf(m, fabsf(w[i]));
#pragma unroll
    for (int off = 16; off > 0; off >>= 1)
        m = fmaxf(m, __shfl_xor_sync(0xffffffffu, m, off));
    __shared__ float sm[8];
    int lane = threadIdx.x & 31, wid = threadIdx.x >> 5;
    if (lane == 0) sm[wid] = m;
    __syncthreads();
    if (threadIdx.x == 0) {
        float mm = sm[0];
        for (int i = 1; i < (int)(blockDim.x >> 5); i++) mm = fmaxf(mm, sm[i]);
        atomicMax(&g_absmax[slot], __float_as_uint(mm)); // nonneg: uint order == float order
    }
}

__device__ __forceinline__ float quant_w(float w, float s) {
    float r = rintf(__fdiv_rn(w, s));   // jnp.round = RNE
    r = fminf(fmaxf(r, -7.f), 7.f);
    return r * s;
}

struct QArgs { const float* src[8]; float* dst[8]; int n[8]; int slot[8]; };

__global__ void k_quant_all(QArgs a) {
    const int i = blockIdx.y;
    float s = __fdiv_rn(__uint_as_float(g_absmax[a.slot[i]]), 7.0f);
    const float* __restrict__ src = a.src[i];
    float* __restrict__ dst = a.dst[i];
    const int n = a.n[i];
    for (int j = blockIdx.x * blockDim.x + threadIdx.x; j < n; j += gridDim.x * blockDim.x)
        dst[j] = quant_w(src[j], s);
}

// fc1 weight: quantize + permute NCHW-flat -> NHWC-flat + transpose to [k][n]
__global__ void k_quantw_fc1t(const float* __restrict__ w, float* __restrict__ wt) {
    float s = __fdiv_rn(__uint_as_float(g_absmax[5]), 7.0f);
    const int KD = 48576;                 // 64*23*33
    for (int i = blockIdx.x * blockDim.x + threadIdx.x; i < 100 * KD; i += gridDim.x * blockDim.x) {
        int nn = i / KD, f = i - nn * KD; // f = c*759 + hw (NCHW flat)
        int c = f / 759, hw = f - c * 759;
        int g = hw * 64 + c;              // NHWC flat
        wt[g * 100 + nn] = quant_w(w[i], s);
    }
}

// fp32 activation quant: identical to reference elementwise chain
__device__ __forceinline__ float qact(float v, float as) {
    v = fmaxf(v, 0.f);
    return fminf(rintf(__fdiv_rn(v, as)), 15.f) * as;
}

// ---------------- conv1: fused sequential (kh,kw) fp32 chain; NHWC output ----------------
__global__ void __launch_bounds__(128)
conv1_nhwc(const float* __restrict__ x, const float* __restrict__ w,
           const float* __restrict__ bias, const float* __restrict__ act_scale,
           float* __restrict__ y)
{
    constexpr int K = 5, S = 2, OCT = 8, P = 4;
    constexpr int Hin = 240, Win = 320, Hout = 118, Wout = 158, COUT = 24;
    __shared__ float sw[OCT * K * K];
    const int oc0 = blockIdx.y * OCT;
    const int n   = blockIdx.z;

    for (int i = threadIdx.x; i < OCT * K * K; i += 128)
        sw[i] = w[oc0 * K * K + i];
    __syncthreads();

    const int npix = Hout * Wout;
    const int p0 = blockIdx.x * (128 * P) + threadIdx.x;

    int xoff[P];
#pragma unroll
    for (int j = 0; j < P; j++) {
        int p = p0 + j * 128;
        int pp = (p < npix) ? p : 0;
        int oh = pp / Wout, ow = pp - oh * Wout;
        xoff[j] = oh * S * Win + ow * S;
    }

    float acc[OCT][P];
#pragma unroll
    for (int oc = 0; oc < OCT; oc++)
#pragma unroll
        for (int j = 0; j < P; j++) acc[oc][j] = 0.f;

    const float* xn = x + (size_t)n * Hin * Win;

#pragma unroll
    for (int kh = 0; kh < K; kh++) {
        const float* xr = xn + kh * Win;
#pragma unroll
        for (int kw = 0; kw < K; kw++) {
            float xv[P];
#pragma unroll
            for (int j = 0; j < P; j++)
                xv[j] = __ldg(xr + xoff[j] + kw);
#pragma unroll
            for (int oc = 0; oc < OCT; oc++) {
                float wv = sw[oc * K * K + kh * K + kw];
#pragma unroll
                for (int j = 0; j < P; j++)
                    acc[oc][j] = fmaf(xv[j], wv, acc[oc][j]);   // single fused chain
            }
        }
    }

    const float as = *act_scale;
    float bb[OCT];
#pragma unroll
    for (int oc = 0; oc < OCT; oc++) bb[oc] = bias[oc0 + oc];

#pragma unroll
    for (int j = 0; j < P; j++) {
        int p = p0 + j * 128;
        if (p < npix) {
            float* yp = y + ((size_t)n * npix + p) * COUT + oc0;
            float4 o0, o1;
            o0.x = qact(acc[0][j] + bb[0], as);
            o0.y = qact(acc[1][j] + bb[1], as);
            o0.z = qact(acc[2][j] + bb[2], as);
            o0.w = qact(acc[3][j] + bb[3], as);
            o1.x = qact(acc[4][j] + bb[4], as);
            o1.y = qact(acc[5][j] + bb[5], as);
            o1.z = qact(acc[6][j] + bb[6], as);
            o1.w = qact(acc[7][j] + bb[7], as);
            *reinterpret_cast<float4*>(yp)     = o0;
            *reinterpret_cast<float4*>(yp + 4) = o1;
        }
    }
}

// ---------------- gmem v8 conv (conv3): R10 proven kernel ----------------
template<int CIN, int COUT, int K, int S, int OCT>
__global__ void __launch_bounds__(128)
conv_v8_nhwc(const float* __restrict__ x, const float* __restrict__ w,
             const float* __restrict__ bias, const float* __restrict__ act_scale,
             float* __restrict__ y, int Hin, int Win, int Hout, int Wout)
{
    constexpr int CKK = CIN * K * K;
    constexpr int WSZ = OCT * CKK;
    constexpr int C8  = CIN / 8;
    __shared__ __align__(16) float sw[WSZ];   // [oc][kh][kw][ci]
    const int oc0 = blockIdx.y * OCT;
    const int n   = blockIdx.z;

    for (int i = threadIdx.x; i < WSZ; i += 128) {
        int oc = i / CKK;
        int rem = i - oc * CKK;
        int kh = rem / (K * CIN);
        rem -= kh * (K * CIN);
        int kw = rem / CIN;
        int ci = rem - kw * CIN;
        sw[i] = w[((oc0 + oc) * CIN + ci) * (K * K) + kh * K + kw];
    }
    __syncthreads();

    const int npix = Hout * Wout;
    const int p = blockIdx.x * 128 + threadIdx.x;
    const int pp = (p < npix) ? p : 0;
    const int oh = pp / Wout, ow = pp - oh * Wout;
    const int xbase = (oh * S * Win + ow * S) * CIN;

    float s[OCT];
#pragma unroll
    for (int oc = 0; oc < OCT; oc++) s[oc] = 0.f;

    const float* xn = x + (size_t)n * Hin * Win * CIN;

#pragma unroll
    for (int kh = 0; kh < K; kh++) {
#pragma unroll
        for (int kw = 0; kw < K; kw++) {
            const int off = (kh * Win + kw) * CIN;
            const int woff = (kh * K + kw) * CIN;

            float v[OCT][8];
#pragma unroll
            for (int oc = 0; oc < OCT; oc++) {
                v[oc][0] = s[oc];
#pragma unroll
                for (int l = 1; l < 8; l++) v[oc][l] = 0.f;
            }

            const float4* xp = reinterpret_cast<const float4*>(xn + xbase + off);
#pragma unroll
            for (int c = 0; c < C8; c++) {
                float4 xa = __ldg(xp + 2 * c);
                float4 xb = __ldg(xp + 2 * c + 1);
#pragma unroll
                for (int oc = 0; oc < OCT; oc++) {
                    const float4* wp = reinterpret_cast<const float4*>(sw + oc * CKK + woff);
                    float4 wa = wp[2 * c], wb = wp[2 * c + 1];
                    v[oc][0] = fmaf(xa.x, wa.x, v[oc][0]);
                    v[oc][1] = fmaf(xa.y, wa.y, v[oc][1]);
                    v[oc][2] = fmaf(xa.z, wa.z, v[oc][2]);
                    v[oc][3] = fmaf(xa.w, wa.w, v[oc][3]);
                    v[oc][4] = fmaf(xb.x, wb.x, v[oc][4]);
                    v[oc][5] = fmaf(xb.y, wb.y, v[oc][5]);
                    v[oc][6] = fmaf(xb.z, wb.z, v[oc][6]);
                    v[oc][7] = fmaf(xb.w, wb.w, v[oc][7]);
                }
            }

            // reduce: IC2 combine (l, l+4) then shuffle-halves tree
#pragma unroll
            for (int oc = 0; oc < OCT; oc++) {
                float h0 = __fadd_rn(v[oc][0], v[oc][4]);
                float h1 = __fadd_rn(v[oc][1], v[oc][5]);
                float h2 = __fadd_rn(v[oc][2], v[oc][6]);
                float h3 = __fadd_rn(v[oc][3], v[oc][7]);
                s[oc] = __fadd_rn(__fadd_rn(h0, h2), __fadd_rn(h1, h3));
            }

            // scalar tail (ci = 8*C8 .. CIN-1), sequential
#pragma unroll
            for (int ci = 8 * C8; ci < CIN; ci++) {
                float xt = __ldg(xn + xbase + off + ci);
#pragma unroll
                for (int oc = 0; oc < OCT; oc++)
                    s[oc] = fmaf(xt, sw[oc * CKK + woff + ci], s[oc]);
            }
        }
    }

    if (p < npix) {
        const float as = *act_scale;
        float* yp = y + ((size_t)n * npix + p) * COUT + oc0;
#pragma unroll
        for (int oq = 0; oq < OCT / 4; oq++) {
            float4 o;
            o.x = qact(s[oq * 4 + 0] + bias[oc0 + oq * 4 + 0], as);
            o.y = qact(s[oq * 4 + 1] + bias[oc0 + oq * 4 + 1], as);
            o.z = qact(s[oq * 4 + 2] + bias[oc0 + oq * 4 + 2], as);
            o.w = qact(s[oq * 4 + 3] + bias[oc0 + oq * 4 + 3], as);
            *reinterpret_cast<float4*>(yp + oq * 4) = o;
        }
    }
}

// ---------------- tiled convs (2, 4, 5): dynamic-SMEM staging, unroll-1 outer loops ----------------
// Block (128 thr = TH x TW pixels) stages its input patch coalesced into SMEM.
// The per-output arithmetic DAG is IDENTICAL to conv_v8_nhwc (v8 lanes ci%8,
// seed in lane 0, IC2 + shuffle-halves tree; CIN % 8 == 0 so no tail).
// #pragma unroll 1 on kh/kw prevents ptxas from hoisting LDS loads across
// iterations (the R11/R12 spill mechanism).
template<int CIN, int COUT, int K, int S, int OCT, int TH, int TW, int PADF4>
__global__ void __launch_bounds__(128)
conv_tile_v8(const float* __restrict__ x, const float* __restrict__ w,
             const float* __restrict__ bias, const float* __restrict__ act_scale,
             float* __restrict__ y, int Hin, int Win, int Hout, int Wout, int CT)
{
    constexpr int CINF4 = CIN / 4;
    constexpr int C8    = CIN / 8;
    constexpr int PH    = TH * S + K - S;
    constexpr int PW    = TW * S + K - S;
    constexpr int CKK   = CIN * K * K;
    constexpr int SXF4  = PH * PW * PADF4;
    static_assert(TH * TW == 128, "one pixel per thread");
    static_assert(CIN % 8 == 0, "no-tail layers only");

    extern __shared__ __align__(16) float4 smem[];
    float4* sx = smem;
    float*  sw = reinterpret_cast<float*>(smem + SXF4);

    const int tid = threadIdx.x;
    const int bt  = blockIdx.x;
    const int tyb = bt / CT, txb = bt - tyb * CT;
    const int oc0 = blockIdx.y * OCT;
    const int n   = blockIdx.z;

    // weights reordered [oc][kh][kw][ci]
    for (int i = tid; i < OCT * CKK; i += 128) {
        int oc = i / CKK;
        int rem = i - oc * CKK;
        int kh = rem / (K * CIN);
        rem -= kh * (K * CIN);
        int kw = rem / CIN;
        int ci = rem - kw * CIN;
        sw[i] = w[((oc0 + oc) * CIN + ci) * (K * K) + kh * K + kw];
    }

    // cooperative coalesced patch load (clamped data only feeds invalid outputs)
    const int ih0 = tyb * TH * S, iw0 = txb * TW * S;
    const float4* xg = reinterpret_cast<const float4*>(x) + (size_t)n * Hin * Win * CINF4;
    for (int i = tid; i < PH * PW * CINF4; i += 128) {
        int pr = i / (PW * CINF4);
        int rem = i - pr * (PW * CINF4);
        int pc = rem / CINF4;
        int f  = rem - pc * CINF4;
        int ir = ih0 + pr; if (ir > Hin - 1) ir = Hin - 1;
        int ic = iw0 + pc; if (ic > Win - 1) ic = Win - 1;
        sx[(pr * PW + pc) * PADF4 + f] = __ldg(xg + ((size_t)ir * Win + ic) * CINF4 + f);
    }
    __syncthreads();

    const int lr = tid / TW, lc = tid - lr * TW;
    const int oh = tyb * TH + lr, ow = txb * TW + lc;
    const bool valid = (oh < Hout) && (ow < Wout);
    const int pbase = (lr * S) * PW + lc * S;

    float s[OCT];
#pragma unroll
    for (int oc = 0; oc < OCT; oc++) s[oc] = 0.f;

#pragma unroll 1
    for (int kh = 0; kh < K; kh++) {
#pragma unroll 1
        for (int kw = 0; kw < K; kw++) {
            const float4* xp = sx + (pbase + kh * PW + kw) * PADF4;
            const float*  wb = sw + (kh * K + kw) * CIN;

            float v[OCT][8];
#pragma unroll
            for (int oc = 0; oc < OCT; oc++) {
                v[oc][0] = s[oc];
#pragma unroll
                for (int l = 1; l < 8; l++) v[oc][l] = 0.f;
            }

#pragma unroll
            for (int c = 0; c < C8; c++) {
                float4 xa = xp[2 * c];
                float4 xb = xp[2 * c + 1];
#pragma unroll
                for (int oc = 0; oc < OCT; oc++) {
                    const float4* wp = reinterpret_cast<const float4*>(wb + oc * CKK);
                    float4 wa = wp[2 * c], wb4 = wp[2 * c + 1];
                    v[oc][0] = fmaf(xa.x, wa.x,  v[oc][0]);
                    v[oc][1] = fmaf(xa.y, wa.y,  v[oc][1]);
                    v[oc][2] = fmaf(xa.z, wa.z,  v[oc][2]);
                    v[oc][3] = fmaf(xa.w, wa.w,  v[oc][3]);
                    v[oc][4] = fmaf(xb.x, wb4.x, v[oc][4]);
                    v[oc][5] = fmaf(xb.y, wb4.y, v[oc][5]);
                    v[oc][6] = fmaf(xb.z, wb4.z, v[oc][6]);
                    v[oc][7] = fmaf(xb.w, wb4.w, v[oc][7]);
                }
            }

            // reduce: IC2 combine (l, l+4) then shuffle-halves tree
#pragma unroll
            for (int oc = 0; oc < OCT; oc++) {
                float h0 = __fadd_rn(v[oc][0], v[oc][4]);
                float h1 = __fadd_rn(v[oc][1], v[oc][5]);
                float h2 = __fadd_rn(v[oc][2], v[oc][6]);
                float h3 = __fadd_rn(v[oc][3], v[oc][7]);
                s[oc] = __fadd_rn(__fadd_rn(h0, h2), __fadd_rn(h1, h3));
            }
        }
    }

    if (valid) {
        const float as = *act_scale;
        float* yp = y + ((size_t)n * Hout * Wout + oh * Wout + ow) * COUT + oc0;
#pragma unroll
        for (int oq = 0; oq < OCT / 4; oq++) {
            float4 o;
            o.x = qact(s[oq * 4 + 0] + bias[oc0 + oq * 4 + 0], as);
            o.y = qact(s[oq * 4 + 1] + bias[oc0 + oq * 4 + 1], as);
            o.z = qact(s[oq * 4 + 2] + bias[oc0 + oq * 4 + 2], as);
            o.w = qact(s[oq * 4 + 3] + bias[oc0 + oq * 4 + 3], as);
            *reinterpret_cast<float4*>(yp + oq * 4) = o;
        }
    }
}

// ---------------- FC1: fp32 split-K, 8-row blocks (FC proven flip-free) ----------------
__global__ void __launch_bounds__(256)
k_fc1_part(const float* __restrict__ A, const float* __restrict__ Wt,
           float* __restrict__ part)
{
    constexpr int KD = 48576;
    constexpr int LEN = KD / FC1_SPLIT;   // 1518
    __shared__ float sA[8][LEN];          // 48,576 B static
    const int tid = threadIdx.x;
    const int m0  = blockIdx.x * 8;
    const int s   = blockIdx.y;
    const int k0  = s * LEN;

    for (int i = tid; i < 8 * LEN; i += 256) {
        int r = i / LEN, k = i - r * LEN;
        sA[r][k] = A[(size_t)(m0 + r) * KD + k0 + k];
    }
    __syncthreads();

    if (tid < 200) {
        int mg = tid / 100, nn = tid - mg * 100;
        const float* wp = Wt + (size_t)k0 * 100 + nn;
        const float* r0 = sA[mg * 4 + 0];
        const float* r1 = sA[mg * 4 + 1];
        const float* r2 = sA[mg * 4 + 2];
        const float* r3 = sA[mg * 4 + 3];
        float a0 = 0.f, a1 = 0.f, a2 = 0.f, a3 = 0.f;
#pragma unroll 4
        for (int k = 0; k < LEN; k++) {
            float wv = __ldg(wp + (size_t)k * 100);
            a0 = fmaf(r0[k], wv, a0);
            a1 = fmaf(r1[k], wv, a1);
            a2 = fmaf(r2[k], wv, a2);
            a3 = fmaf(r3[k], wv, a3);
        }
        int mb = m0 + mg * 4;
        part[(s * 128 + mb + 0) * 100 + nn] = a0;
        part[(s * 128 + mb + 1) * 100 + nn] = a1;
        part[(s * 128 + mb + 2) * 100 + nn] = a2;
        part[(s * 128 + mb + 3) * 100 + nn] = a3;
    }
}

__global__ void k_fc1_epi(const float* __restrict__ part,
                          const float* __restrict__ bias,
                          const float* __restrict__ act_scale,
                          float* __restrict__ out)
{
    int idx = blockIdx.x * blockDim.x + threadIdx.x;
    if (idx >= 128 * 100) return;
    float v = 0.f;
    for (int s = 0; s < FC1_SPLIT; s++) v += part[s * 12800 + idx];  // fixed order
    int nn = idx % 100;
    float f = v + bias[nn];
    out[idx] = qact(f, *act_scale);
}

// ---------------- small FC layers, fp64 (tiny; keep exact) ----------------
__global__ void k_fc_small(const float* __restrict__ A, const float* __restrict__ W,
                           const float* __restrict__ bias, const float* __restrict__ act_scale,
                           float* __restrict__ C, int N, int Kd)
{
    int idx = blockIdx.x * blockDim.x + threadIdx.x;
    if (idx >= 128 * N) return;
    int m = idx / N, nn = idx - m * N;
    const float* a = A + m * Kd;
    const float* w = W + nn * Kd;
    double acc = 0.0;
    for (int k = 0; k < Kd; k++) acc = fma((double)__ldg(a + k), (double)__ldg(w + k), acc);
    float f = (float)acc + bias[nn];
    C[idx] = qact(f, *act_scale);
}

__global__ void k_out(const float* __restrict__ f3, const float* __restrict__ ow_q,
                      const float* __restrict__ ob, float* __restrict__ out)
{
    int m = blockIdx.x * blockDim.x + threadIdx.x;
    if (m >= 128) return;
    double acc = 0.0;
#pragma unroll
    for (int k = 0; k < 10; k++) acc = fma((double)f3[m * 10 + k], (double)ow_q[k], acc);
    out[m] = (float)acc + ob[0];
}

// ---------------- host ----------------
extern "C" void kernel_launch(void* const* d_in, const int* in_sizes, int n_in,
                              void* d_out, int out_size)
{
    const float* x   = (const float*)d_in[0];
    const float* cw[5] = {(const float*)d_in[1], (const float*)d_in[3], (const float*)d_in[5],
                          (const float*)d_in[7], (const float*)d_in[9]};
    const float* cb[5] = {(const float*)d_in[2], (const float*)d_in[4], (const float*)d_in[6],
                          (const float*)d_in[8], (const float*)d_in[10]};
    const float* fw[3] = {(const float*)d_in[11], (const float*)d_in[13], (const float*)d_in[15]};
    const float* fb[3] = {(const float*)d_in[12], (const float*)d_in[14], (const float*)d_in[16]};
    const float* oww = (const float*)d_in[17];
    const float* obb = (const float*)d_in[18];
    const float* as  = (const float*)d_in[19];

    void *a1p, *a2p, *a3p, *a4p, *a5p;
    void *q1p, *q2p, *q3p, *q4p, *q5p, *qf1tp, *qf2p, *qf3p, *qowp;
    void *partp, *f1p, *f2p, *f3p;
    cudaGetSymbolAddress(&a1p, g_a1);   cudaGetSymbolAddress(&a2p, g_a2);
    cudaGetSymbolAddress(&a3p, g_a3);   cudaGetSymbolAddress(&a4p, g_a4);
    cudaGetSymbolAddress(&a5p, g_a5);
    cudaGetSymbolAddress(&q1p, g_qw1);  cudaGetSymbolAddress(&q2p, g_qw2);
    cudaGetSymbolAddress(&q3p, g_qw3);  cudaGetSymbolAddress(&q4p, g_qw4);
    cudaGetSymbolAddress(&q5p, g_qw5);
    cudaGetSymbolAddress(&qf1tp, g_qfw1t); cudaGetSymbolAddress(&qf2p, g_qfw2);
    cudaGetSymbolAddress(&qf3p, g_qfw3);   cudaGetSymbolAddress(&qowp, g_qow);
    cudaGetSymbolAddress(&partp, g_fc1part);
    cudaGetSymbolAddress(&f1p, g_f1);   cudaGetSymbolAddress(&f2p, g_f2);
    cudaGetSymbolAddress(&f3p, g_f3);

    float* a1 = (float*)a1p; float* a2 = (float*)a2p; float* a3 = (float*)a3p;
    float* a4 = (float*)a4p; float* a5 = (float*)a5p;

    // tiled conv instantiations + dynamic smem opt-in (mechanism proven in R11)
    auto conv2k = conv_tile_v8<24, 36, 5, 2, 12, 8, 16, 7>;
    auto conv4k = conv_tile_v8<48, 64, 3, 1, 8,  8, 16, 13>;
    auto conv5k = conv_tile_v8<64, 64, 3, 1, 8,  8, 16, 17>;
    const int smem2 = 19 * 35 * 7 * 16 + 12 * 600 * 4;   // 74480 + 28800 = 103280
    const int smem4 = 10 * 18 * 13 * 16 + 8 * 432 * 4;   // 37440 + 13824 = 51264
    const int smem5 = 10 * 18 * 17 * 16 + 8 * 576 * 4;   // 48960 + 18432 = 67392
    cudaFuncSetAttribute(conv2k, cudaFuncAttributeMaxDynamicSharedMemorySize, smem2);
    cudaFuncSetAttribute(conv4k, cudaFuncAttributeMaxDynamicSharedMemorySize, smem4);
    cudaFuncSetAttribute(conv5k, cudaFuncAttributeMaxDynamicSharedMemorySize, smem5);

    // ---- weight quantization (merged) ----
    k_reset_absmax<<<1, 32>>>();

    const int qn[9] = {24*1*5*5, 36*24*5*5, 48*36*5*5, 64*48*3*3, 64*64*3*3,
                       100*48576, 50*100, 10*50, 10};
    AbsArgs aa;
    aa.p[0] = cw[0]; aa.p[1] = cw[1]; aa.p[2] = cw[2]; aa.p[3] = cw[3]; aa.p[4] = cw[4];
    aa.p[5] = fw[0]; aa.p[6] = fw[1]; aa.p[7] = fw[2]; aa.p[8] = oww;
    for (int i = 0; i < 9; i++) aa.n[i] = qn[i];
    k_absmax_all<<<dim3(64, 9), 256>>>(aa);

    QArgs qa;
    qa.src[0] = cw[0]; qa.dst[0] = (float*)q1p;  qa.n[0] = qn[0]; qa.slot[0] = 0;
    qa.src[1] = cw[1]; qa.dst[1] = (float*)q2p;  qa.n[1] = qn[1]; qa.slot[1] = 1;
    qa.src[2] = cw[2]; qa.dst[2] = (float*)q3p;  qa.n[2] = qn[2]; qa.slot[2] = 2;
    qa.src[3] = cw[3]; qa.dst[3] = (float*)q4p;  qa.n[3] = qn[3]; qa.slot[3] = 3;
    qa.src[4] = cw[4]; qa.dst[4] = (float*)q5p;  qa.n[4] = qn[4]; qa.slot[4] = 4;
    qa.src[5] = fw[1]; qa.dst[5] = (float*)qf2p; qa.n[5] = qn[6]; qa.slot[5] = 6;
    qa.src[6] = fw[2]; qa.dst[6] = (float*)qf3p; qa.n[6] = qn[7]; qa.slot[6] = 7;
    qa.src[7] = oww;   qa.dst[7] = (float*)qowp; qa.n[7] = qn[8]; qa.slot[7] = 8;
    k_quant_all<<<dim3(32, 8), 256>>>(qa);

    k_quantw_fc1t<<<4096, 256>>>(fw[0], (float*)qf1tp);

    // ---- conv1 ----
    conv1_nhwc<<<dim3(DIVUP(118*158, 512), 3, 128), 128>>>(
        x, (float*)q1p, cb[0], as, a1);

    // ---- conv2: tiled (ncu capture slot) ----
    conv2k<<<dim3(DIVUP(77,16) * DIVUP(57,8), 3, 128), 128, smem2>>>(
        a1, (float*)q2p, cb[1], as, a2, 118, 158, 57, 77, DIVUP(77,16));

    // ---- conv3: gmem v8 (CIN=36 tail layer) ----
    conv_v8_nhwc<36, 48, 5, 2, 16><<<dim3(DIVUP(27*37, 128), 3, 128), 128>>>(
        a2, (float*)q3p, cb[2], as, a3, 57, 77, 27, 37);

    // ---- conv4, conv5: tiled ----
    conv4k<<<dim3(DIVUP(35,16) * DIVUP(25,8), 8, 128), 128, smem4>>>(
        a3, (float*)q4p, cb[3], as, a4, 27, 37, 25, 35, DIVUP(35,16));
    conv5k<<<dim3(DIVUP(33,16) * DIVUP(23,8), 8, 128), 128, smem5>>>(
        a4, (float*)q5p, cb[4], as, a5, 25, 35, 23, 33, DIVUP(33,16));

    // ---- FC layers ----
    k_fc1_part<<<dim3(16, FC1_SPLIT), 256>>>(a5, (float*)qf1tp, (float*)partp);
    k_fc1_epi<<<DIVUP(128*100, 256), 256>>>((float*)partp, fb[0], as, (float*)f1p);
    k_fc_small<<<DIVUP(128*50, 128), 128>>>((float*)f1p, (float*)qf2p, fb[1], as, (float*)f2p, 50, 100);
    k_fc_small<<<DIVUP(128*10, 128), 128>>>((float*)f2p, (float*)qf3p, fb[2], as, (float*)f3p, 10, 50);
    k_out<<<1, 128>>>((float*)f3p, (float*)qowp, obb, (float*)d_out);
}

// round 15
// speedup vs baseline: 1.0676x; 1.0676x over previous
#include <cuda_runtime.h>
#include <cstdint>

#define DIVUP(a,b) (((a)+(b)-1)/(b))

// ---------------- static scratch (no allocations allowed) ----------------
// Activations in NHWC layout: [n][h][w][c]
__device__ float g_a1[128*118*158*24];
__device__ float g_a2[128*57*77*36];
__device__ float g_a3[128*27*37*48];
__device__ float g_a4[128*25*35*64];
__device__ float g_a5[128*23*33*64];

__device__ float g_qw1[24*1*5*5];
__device__ float g_qw2[36*24*5*5];
__device__ float g_qw3[48*36*5*5];
__device__ float g_qw4[64*48*3*3];
__device__ float g_qw5[64*64*3*3];
__device__ float g_qfw1t[48576*100];     // fc1 weight: quantized, NHWC-permuted, [k][n]
__device__ float g_qfw2[50*100];
__device__ float g_qfw3[10*50];
__device__ float g_qow[10];

__device__ unsigned g_absmax[9];

#define FC1_SPLIT 32
__device__ float g_fc1part[FC1_SPLIT*128*100];
__device__ float g_f1[128*100];
__device__ float g_f2[128*50];
__device__ float g_f3[128*10];

// ---------------- merged weight fake-quant (exact fp32 semantics) ----------------
__global__ void k_reset_absmax() {
    if (threadIdx.x < 9) g_absmax[threadIdx.x] = 0u;
}

struct AbsArgs { const float* p[9]; int n[9]; };

__global__ void k_absmax_all(AbsArgs a) {
    const int slot = blockIdx.y;
    const float* __restrict__ w = a.p[slot];
    const int n = a.n[slot];
    float m = 0.f;
    for (int i = blockIdx.x * blockDim.x + threadIdx.x; i < n; i += gridDim.x * blockDim.x)
        m = fmaxf(m, fabsf(w[i]));
#pragma unroll
    for (int off = 16; off > 0; off >>= 1)
        m = fmaxf(m, __shfl_xor_sync(0xffffffffu, m, off));
    __shared__ float sm[8];
    int lane = threadIdx.x & 31, wid = threadIdx.x >> 5;
    if (lane == 0) sm[wid] = m;
    __syncthreads();
    if (threadIdx.x == 0) {
        float mm = sm[0];
        for (int i = 1; i < (int)(blockDim.x >> 5); i++) mm = fmaxf(mm, sm[i]);
        atomicMax(&g_absmax[slot], __float_as_uint(mm)); // nonneg: uint order == float order
    }
}

__device__ __forceinline__ float quant_w(float w, float s) {
    float r = rintf(__fdiv_rn(w, s));   // jnp.round = RNE
    r = fminf(fmaxf(r, -7.f), 7.f);
    return r * s;
}

struct QArgs { const float* src[8]; float* dst[8]; int n[8]; int slot[8]; };

__global__ void k_quant_all(QArgs a) {
    const int i = blockIdx.y;
    float s = __fdiv_rn(__uint_as_float(g_absmax[a.slot[i]]), 7.0f);
    const float* __restrict__ src = a.src[i];
    float* __restrict__ dst = a.dst[i];
    const int n = a.n[i];
    for (int j = blockIdx.x * blockDim.x + threadIdx.x; j < n; j += gridDim.x * blockDim.x)
        dst[j] = quant_w(src[j], s);
}

// fc1 weight: quantize + permute NCHW-flat -> NHWC-flat + transpose to [k][n]
__global__ void k_quantw_fc1t(const float* __restrict__ w, float* __restrict__ wt) {
    float s = __fdiv_rn(__uint_as_float(g_absmax[5]), 7.0f);
    const int KD = 48576;                 // 64*23*33
    for (int i = blockIdx.x * blockDim.x + threadIdx.x; i < 100 * KD; i += gridDim.x * blockDim.x) {
        int nn = i / KD, f = i - nn * KD; // f = c*759 + hw (NCHW flat)
        int c = f / 759, hw = f - c * 759;
        int g = hw * 64 + c;              // NHWC flat
        wt[g * 100 + nn] = quant_w(w[i], s);
    }
}

// fp32 activation quant: identical to reference elementwise chain
__device__ __forceinline__ float qact(float v, float as) {
    v = fmaxf(v, 0.f);
    return fminf(rintf(__fdiv_rn(v, as)), 15.f) * as;
}

// ---------------- conv1: fused sequential (kh,kw) fp32 chain; NHWC output ----------------
// CONTRACT-LOCKED: this exact chain is required to match the reference.
__global__ void __launch_bounds__(128)
conv1_nhwc(const float* __restrict__ x, const float* __restrict__ w,
           const float* __restrict__ bias, const float* __restrict__ act_scale,
           float* __restrict__ y)
{
    constexpr int K = 5, S = 2, OCT = 8, P = 4;
    constexpr int Hin = 240, Win = 320, Hout = 118, Wout = 158, COUT = 24;
    __shared__ float sw[OCT * K * K];
    const int oc0 = blockIdx.y * OCT;
    const int n   = blockIdx.z;

    for (int i = threadIdx.x; i < OCT * K * K; i += 128)
        sw[i] = w[oc0 * K * K + i];
    __syncthreads();

    const int npix = Hout * Wout;
    const int p0 = blockIdx.x * (128 * P) + threadIdx.x;

    int xoff[P];
#pragma unroll
    for (int j = 0; j < P; j++) {
        int p = p0 + j * 128;
        int pp = (p < npix) ? p : 0;
        int oh = pp / Wout, ow = pp - oh * Wout;
        xoff[j] = oh * S * Win + ow * S;
    }

    float acc[OCT][P];
#pragma unroll
    for (int oc = 0; oc < OCT; oc++)
#pragma unroll
        for (int j = 0; j < P; j++) acc[oc][j] = 0.f;

    const float* xn = x + (size_t)n * Hin * Win;

#pragma unroll
    for (int kh = 0; kh < K; kh++) {
        const float* xr = xn + kh * Win;
#pragma unroll
        for (int kw = 0; kw < K; kw++) {
            float xv[P];
#pragma unroll
            for (int j = 0; j < P; j++)
                xv[j] = __ldg(xr + xoff[j] + kw);
#pragma unroll
            for (int oc = 0; oc < OCT; oc++) {
                float wv = sw[oc * K * K + kh * K + kw];
#pragma unroll
                for (int j = 0; j < P; j++)
                    acc[oc][j] = fmaf(xv[j], wv, acc[oc][j]);   // single fused chain
            }
        }
    }

    const float as = *act_scale;
    float bb[OCT];
#pragma unroll
    for (int oc = 0; oc < OCT; oc++) bb[oc] = bias[oc0 + oc];

#pragma unroll
    for (int j = 0; j < P; j++) {
        int p = p0 + j * 128;
        if (p < npix) {
            float* yp = y + ((size_t)n * npix + p) * COUT + oc0;
            float4 o0, o1;
            o0.x = qact(acc[0][j] + bb[0], as);
            o0.y = qact(acc[1][j] + bb[1], as);
            o0.z = qact(acc[2][j] + bb[2], as);
            o0.w = qact(acc[3][j] + bb[3], as);
            o1.x = qact(acc[4][j] + bb[4], as);
            o1.y = qact(acc[5][j] + bb[5], as);
            o1.z = qact(acc[6][j] + bb[6], as);
            o1.w = qact(acc[7][j] + bb[7], as);
            *reinterpret_cast<float4*>(yp)     = o0;
            *reinterpret_cast<float4*>(yp + 4) = o1;
        }
    }
}

// ---------------- convs 2-5: hoisted 8-lane accumulators (single final reduce) ----------------
// Lane accumulators v[oc][0..7] persist across the whole (kh,kw,ci) reduction:
// inner body is pure FMA (+ weight LDS), one IC2 + shuffle-halves tree at the
// end. Noise is LOWER than the per-window-reduce v8 DAG (fewer roundings),
// which was proven bit-equivalent to fp64-exact — stays under the quantization
// no-flip gap. Tail (CIN % 8, conv3 only) folds into lanes 0..tail-1.
template<int CIN, int COUT, int K, int S, int OCT>
__global__ void __launch_bounds__(128)
conv_v8h_nhwc(const float* __restrict__ x, const float* __restrict__ w,
              const float* __restrict__ bias, const float* __restrict__ act_scale,
              float* __restrict__ y, int Hin, int Win, int Hout, int Wout)
{
    constexpr int CKK = CIN * K * K;
    constexpr int WSZ = OCT * CKK;
    constexpr int C8  = CIN / 8;
    constexpr int TAIL = CIN - 8 * C8;
    __shared__ __align__(16) float sw[WSZ];   // [oc][kh][kw][ci]
    const int oc0 = blockIdx.y * OCT;
    const int n   = blockIdx.z;

    for (int i = threadIdx.x; i < WSZ; i += 128) {
        int oc = i / CKK;
        int rem = i - oc * CKK;
        int kh = rem / (K * CIN);
        rem -= kh * (K * CIN);
        int kw = rem / CIN;
        int ci = rem - kw * CIN;
        sw[i] = w[((oc0 + oc) * CIN + ci) * (K * K) + kh * K + kw];
    }
    __syncthreads();

    const int npix = Hout * Wout;
    const int p = blockIdx.x * 128 + threadIdx.x;
    const int pp = (p < npix) ? p : 0;
    const int oh = pp / Wout, ow = pp - oh * Wout;
    const int xbase = (oh * S * Win + ow * S) * CIN;

    float v[OCT][8];
#pragma unroll
    for (int oc = 0; oc < OCT; oc++)
#pragma unroll
        for (int l = 0; l < 8; l++) v[oc][l] = 0.f;

    const float* xn = x + (size_t)n * Hin * Win * CIN;

#pragma unroll
    for (int kh = 0; kh < K; kh++) {
#pragma unroll
        for (int kw = 0; kw < K; kw++) {
            const int off = (kh * Win + kw) * CIN;
            const int woff = (kh * K + kw) * CIN;

            const float4* xp = reinterpret_cast<const float4*>(xn + xbase + off);
#pragma unroll
            for (int c = 0; c < C8; c++) {
                float4 xa = __ldg(xp + 2 * c);
                float4 xb = __ldg(xp + 2 * c + 1);
#pragma unroll
                for (int oc = 0; oc < OCT; oc++) {
                    const float4* wp = reinterpret_cast<const float4*>(sw + oc * CKK + woff);
                    float4 wa = wp[2 * c], wb = wp[2 * c + 1];
                    v[oc][0] = fmaf(xa.x, wa.x, v[oc][0]);
                    v[oc][1] = fmaf(xa.y, wa.y, v[oc][1]);
                    v[oc][2] = fmaf(xa.z, wa.z, v[oc][2]);
                    v[oc][3] = fmaf(xa.w, wa.w, v[oc][3]);
                    v[oc][4] = fmaf(xb.x, wb.x, v[oc][4]);
                    v[oc][5] = fmaf(xb.y, wb.y, v[oc][5]);
                    v[oc][6] = fmaf(xb.z, wb.z, v[oc][6]);
                    v[oc][7] = fmaf(xb.w, wb.w, v[oc][7]);
                }
            }

            // tail (conv3: CIN=36 -> 4 leftovers), folded into lanes 0..TAIL-1
            if (TAIL > 0) {
#pragma unroll
                for (int t = 0; t < TAIL; t++) {
                    float xt = __ldg(xn + xbase + off + 8 * C8 + t);
#pragma unroll
                    for (int oc = 0; oc < OCT; oc++)
                        v[oc][t] = fmaf(xt, sw[oc * CKK + woff + 8 * C8 + t], v[oc][t]);
                }
            }
        }
    }

    if (p < npix) {
        const float as = *act_scale;
        float* yp = y + ((size_t)n * npix + p) * COUT + oc0;
#pragma unroll
        for (int oq = 0; oq < OCT / 4; oq++) {
            float o4[4];
#pragma unroll
            for (int k4 = 0; k4 < 4; k4++) {
                int oc = oq * 4 + k4;
                float h0 = __fadd_rn(v[oc][0], v[oc][4]);
                float h1 = __fadd_rn(v[oc][1], v[oc][5]);
                float h2 = __fadd_rn(v[oc][2], v[oc][6]);
                float h3 = __fadd_rn(v[oc][3], v[oc][7]);
                float s  = __fadd_rn(__fadd_rn(h0, h2), __fadd_rn(h1, h3));
                o4[k4] = qact(s + bias[oc0 + oc], as);
            }
            float4 o;
            o.x = o4[0]; o.y = o4[1]; o.z = o4[2]; o.w = o4[3];
            *reinterpret_cast<float4*>(yp + oq * 4) = o;
        }
    }
}

// ---------------- FC1: fp32 split-K, 8-row blocks (FC proven flip-free) ----------------
__global__ void __launch_bounds__(256)
k_fc1_part(const float* __restrict__ A, const float* __restrict__ Wt,
           float* __restrict__ part)
{
    constexpr int KD = 48576;
    constexpr int LEN = KD / FC1_SPLIT;   // 1518
    __shared__ float sA[8][LEN];          // 48,576 B static
    const int tid = threadIdx.x;
    const int m0  = blockIdx.x * 8;
    const int s   = blockIdx.y;
    const int k0  = s * LEN;

    for (int i = tid; i < 8 * LEN; i += 256) {
        int r = i / LEN, k = i - r * LEN;
        sA[r][k] = A[(size_t)(m0 + r) * KD + k0 + k];
    }
    __syncthreads();

    if (tid < 200) {
        int mg = tid / 100, nn = tid - mg * 100;
        const float* wp = Wt + (size_t)k0 * 100 + nn;
        const float* r0 = sA[mg * 4 + 0];
        const float* r1 = sA[mg * 4 + 1];
        const float* r2 = sA[mg * 4 + 2];
        const float* r3 = sA[mg * 4 + 3];
        float a0 = 0.f, a1 = 0.f, a2 = 0.f, a3 = 0.f;
#pragma unroll 4
        for (int k = 0; k < LEN; k++) {
            float wv = __ldg(wp + (size_t)k * 100);
            a0 = fmaf(r0[k], wv, a0);
            a1 = fmaf(r1[k], wv, a1);
            a2 = fmaf(r2[k], wv, a2);
            a3 = fmaf(r3[k], wv, a3);
        }
        int mb = m0 + mg * 4;
        part[(s * 128 + mb + 0) * 100 + nn] = a0;
        part[(s * 128 + mb + 1) * 100 + nn] = a1;
        part[(s * 128 + mb + 2) * 100 + nn] = a2;
        part[(s * 128 + mb + 3) * 100 + nn] = a3;
    }
}

__global__ void k_fc1_epi(const float* __restrict__ part,
                          const float* __restrict__ bias,
                          const float* __restrict__ act_scale,
                          float* __restrict__ out)
{
    int idx = blockIdx.x * blockDim.x + threadIdx.x;
    if (idx >= 128 * 100) return;
    float v = 0.f;
    for (int s = 0; s < FC1_SPLIT; s++) v += part[s * 12800 + idx];  // fixed order
    int nn = idx % 100;
    float f = v + bias[nn];
    out[idx] = qact(f, *act_scale);
}

// ---------------- small FC layers, fp64 (tiny; keep exact) ----------------
__global__ void k_fc_small(const float* __restrict__ A, const float* __restrict__ W,
                           const float* __restrict__ bias, const float* __restrict__ act_scale,
                           float* __restrict__ C, int N, int Kd)
{
    int idx = blockIdx.x * blockDim.x + threadIdx.x;
    if (idx >= 128 * N) return;
    int m = idx / N, nn = idx - m * N;
    const float* a = A + m * Kd;
    const float* w = W + nn * Kd;
    double acc = 0.0;
    for (int k = 0; k < Kd; k++) acc = fma((double)__ldg(a + k), (double)__ldg(w + k), acc);
    float f = (float)acc + bias[nn];
    C[idx] = qact(f, *act_scale);
}

__global__ void k_out(const float* __restrict__ f3, const float* __restrict__ ow_q,
                      const float* __restrict__ ob, float* __restrict__ out)
{
    int m = blockIdx.x * blockDim.x + threadIdx.x;
    if (m >= 128) return;
    double acc = 0.0;
#pragma unroll
    for (int k = 0; k < 10; k++) acc = fma((double)f3[m * 10 + k], (double)ow_q[k], acc);
    out[m] = (float)acc + ob[0];
}

// ---------------- host ----------------
extern "C" void kernel_launch(void* const* d_in, const int* in_sizes, int n_in,
                              void* d_out, int out_size)
{
    const float* x   = (const float*)d_in[0];
    const float* cw[5] = {(const float*)d_in[1], (const float*)d_in[3], (const float*)d_in[5],
                          (const float*)d_in[7], (const float*)d_in[9]};
    const float* cb[5] = {(const float*)d_in[2], (const float*)d_in[4], (const float*)d_in[6],
                          (const float*)d_in[8], (const float*)d_in[10]};
    const float* fw[3] = {(const float*)d_in[11], (const float*)d_in[13], (const float*)d_in[15]};
    const float* fb[3] = {(const float*)d_in[12], (const float*)d_in[14], (const float*)d_in[16]};
    const float* oww = (const float*)d_in[17];
    const float* obb = (const float*)d_in[18];
    const float* as  = (const float*)d_in[19];

    void *a1p, *a2p, *a3p, *a4p, *a5p;
    void *q1p, *q2p, *q3p, *q4p, *q5p, *qf1tp, *qf2p, *qf3p, *qowp;
    void *partp, *f1p, *f2p, *f3p;
    cudaGetSymbolAddress(&a1p, g_a1);   cudaGetSymbolAddress(&a2p, g_a2);
    cudaGetSymbolAddress(&a3p, g_a3);   cudaGetSymbolAddress(&a4p, g_a4);
    cudaGetSymbolAddress(&a5p, g_a5);
    cudaGetSymbolAddress(&q1p, g_qw1);  cudaGetSymbolAddress(&q2p, g_qw2);
    cudaGetSymbolAddress(&q3p, g_qw3);  cudaGetSymbolAddress(&q4p, g_qw4);
    cudaGetSymbolAddress(&q5p, g_qw5);
    cudaGetSymbolAddress(&qf1tp, g_qfw1t); cudaGetSymbolAddress(&qf2p, g_qfw2);
    cudaGetSymbolAddress(&qf3p, g_qfw3);   cudaGetSymbolAddress(&qowp, g_qow);
    cudaGetSymbolAddress(&partp, g_fc1part);
    cudaGetSymbolAddress(&f1p, g_f1);   cudaGetSymbolAddress(&f2p, g_f2);
    cudaGetSymbolAddress(&f3p, g_f3);

    float* a1 = (float*)a1p; float* a2 = (float*)a2p; float* a3 = (float*)a3p;
    float* a4 = (float*)a4p; float* a5 = (float*)a5p;

    // ---- weight quantization (merged) ----
    k_reset_absmax<<<1, 32>>>();

    const int qn[9] = {24*1*5*5, 36*24*5*5, 48*36*5*5, 64*48*3*3, 64*64*3*3,
                       100*48576, 50*100, 10*50, 10};
    AbsArgs aa;
    aa.p[0] = cw[0]; aa.p[1] = cw[1]; aa.p[2] = cw[2]; aa.p[3] = cw[3]; aa.p[4] = cw[4];
    aa.p[5] = fw[0]; aa.p[6] = fw[1]; aa.p[7] = fw[2]; aa.p[8] = oww;
    for (int i = 0; i < 9; i++) aa.n[i] = qn[i];
    k_absmax_all<<<dim3(64, 9), 256>>>(aa);

    QArgs qa;
    qa.src[0] = cw[0]; qa.dst[0] = (float*)q1p;  qa.n[0] = qn[0]; qa.slot[0] = 0;
    qa.src[1] = cw[1]; qa.dst[1] = (float*)q2p;  qa.n[1] = qn[1]; qa.slot[1] = 1;
    qa.src[2] = cw[2]; qa.dst[2] = (float*)q3p;  qa.n[2] = qn[2]; qa.slot[2] = 2;
    qa.src[3] = cw[3]; qa.dst[3] = (float*)q4p;  qa.n[3] = qn[3]; qa.slot[3] = 3;
    qa.src[4] = cw[4]; qa.dst[4] = (float*)q5p;  qa.n[4] = qn[4]; qa.slot[4] = 4;
    qa.src[5] = fw[1]; qa.dst[5] = (float*)qf2p; qa.n[5] = qn[6]; qa.slot[5] = 6;
    qa.src[6] = fw[2]; qa.dst[6] = (float*)qf3p; qa.n[6] = qn[7]; qa.slot[6] = 7;
    qa.src[7] = oww;   qa.dst[7] = (float*)qowp; qa.n[7] = qn[8]; qa.slot[7] = 8;
    k_quant_all<<<dim3(32, 8), 256>>>(qa);

    k_quantw_fc1t<<<4096, 256>>>(fw[0], (float*)qf1tp);

    // ---- conv1 ----
    conv1_nhwc<<<dim3(DIVUP(118*158, 512), 3, 128), 128>>>(
        x, (float*)q1p, cb[0], as, a1);

    // ---- convs 2-5: hoisted-accumulator v8 ----
    conv_v8h_nhwc<24, 36, 5, 2, 12><<<dim3(DIVUP(57*77, 128), 3, 128), 128>>>(
        a1, (float*)q2p, cb[1], as, a2, 118, 158, 57, 77);
    conv_v8h_nhwc<36, 48, 5, 2, 16><<<dim3(DIVUP(27*37, 128), 3, 128), 128>>>(
        a2, (float*)q3p, cb[2], as, a3, 57, 77, 27, 37);
    conv_v8h_nhwc<48, 64, 3, 1, 16><<<dim3(DIVUP(25*35, 128), 4, 128), 128>>>(
        a3, (float*)q4p, cb[3], as, a4, 27, 37, 25, 35);
    conv_v8h_nhwc<64, 64, 3, 1, 16><<<dim3(DIVUP(23*33, 128), 4, 128), 128>>>(
        a4, (float*)q5p, cb[4], as, a5, 25, 35, 23, 33);

    // ---- FC layers ----
    k_fc1_part<<<dim3(16, FC1_SPLIT), 256>>>(a5, (float*)qf1tp, (float*)partp);
    k_fc1_epi<<<DIVUP(128*100, 256), 256>>>((float*)partp, fb[0], as, (float*)f1p);
    k_fc_small<<<DIVUP(128*50, 128), 128>>>((float*)f1p, (float*)qf2p, fb[1], as, (float*)f2p, 50, 100);
    k_fc_small<<<DIVUP(128*10, 128), 128>>>((float*)f2p, (float*)qf3p, fb[2], as, (float*)f3p, 10, 50);
    k_out<<<1, 128>>>((float*)f3p, (float*)qowp, obb, (float*)d_out);
}